// round 4
// baseline (speedup 1.0000x reference)
#include <cuda_runtime.h>
#include <math.h>

#define NBLOCKS  740             // 148 SMs * 5 blocks (regs ~46 -> 5 CTAs/SM)
#define NTHREADS 256
#define UNROLL   8

__device__ float        g_partials[NBLOCKS];
__device__ unsigned int g_ticket = 0;

__device__ __forceinline__ float rsqrt_approx(float x) {
    float r;
    asm("rsqrt.approx.f32 %0, %1;" : "=f"(r) : "f"(x));
    return r;
}

// lanes 4j..4j+3 hold the 4 segments of one row; combine, then return this
// lane's share of (|row|-1)^2 (i.e. 0.25x in each of the 4 lanes).
__device__ __forceinline__ float quad_loss(float s, bool active) {
    s += __shfl_xor_sync(0xFFFFFFFFu, s, 1);
    s += __shfl_xor_sync(0xFFFFFFFFu, s, 2);
    float r = s * rsqrt_approx(s) - 1.0f;   // sqrt(s) - 1, one MUFU.RSQ
    return active ? 0.25f * r * r : 0.0f;
}

__device__ __forceinline__ float sq4(float4 f) {
    return f.x * f.x + f.y * f.y + f.z * f.z + f.w * f.w;
}

__global__ void __launch_bounds__(NTHREADS)
loss_kernel(const float4* __restrict__ y4, long long nvec,
            float* __restrict__ out, float inv_scale) {
    const long long tid = (long long)blockIdx.x * NTHREADS + threadIdx.x;
    const long long T   = (long long)NBLOCKS * NTHREADS;   // multiple of 4

    const long long kfull = nvec / (UNROLL * T);   // uniform trip count

    float acc = 0.0f;
    for (long long k = 0; k < kfull; k++) {
        long long v = tid + k * (UNROLL * T);
        float4 f[UNROLL];
        #pragma unroll
        for (int u = 0; u < UNROLL; u++)          // 8 front-batched LDG.128
            f[u] = __ldcs(&y4[v + (long long)u * T]);
        #pragma unroll
        for (int u = 0; u < UNROLL; u++)
            acc += quad_loss(sq4(f[u]), true);
    }

    // Predicated uniform tail (nvec % 4 == 0 -> quad-uniform activity)
    {
        long long base = kfull * (UNROLL * T);
        #pragma unroll
        for (int t = 0; t < UNROLL; t++) {
            long long v = base + (long long)t * T + tid;
            bool active = v < nvec;
            float s = active ? sq4(__ldcs(&y4[v])) : 0.0f;
            acc += quad_loss(s, active);
        }
    }

    // block reduction
    #pragma unroll
    for (int m = 16; m > 0; m >>= 1)
        acc += __shfl_xor_sync(0xFFFFFFFFu, acc, m);

    __shared__ float warp_sums[NTHREADS / 32];
    int wid = threadIdx.x >> 5;
    int lid = threadIdx.x & 31;
    if (lid == 0) warp_sums[wid] = acc;
    __syncthreads();

    if (wid == 0) {
        float b = (lid < NTHREADS / 32) ? warp_sums[lid] : 0.0f;
        #pragma unroll
        for (int m = 4; m > 0; m >>= 1)
            b += __shfl_xor_sync(0xFFFFFFFFu, b, m);
        if (lid == 0)
            g_partials[blockIdx.x] = b;
    }

    // single-kernel fan-in: last block reduces the partials
    __shared__ bool is_last;
    __threadfence();
    if (threadIdx.x == 0) {
        unsigned int old = atomicAdd(&g_ticket, 1u);
        is_last = (old == (unsigned)gridDim.x - 1u);
    }
    __syncthreads();

    if (is_last) {
        float s = 0.0f;
        for (int i = threadIdx.x; i < (int)gridDim.x; i += NTHREADS)
            s += g_partials[i];
        #pragma unroll
        for (int m = 16; m > 0; m >>= 1)
            s += __shfl_xor_sync(0xFFFFFFFFu, s, m);
        if (lid == 0) warp_sums[wid] = s;
        __syncthreads();
        if (wid == 0) {
            float b = (lid < NTHREADS / 32) ? warp_sums[lid] : 0.0f;
            #pragma unroll
            for (int m = 4; m > 0; m >>= 1)
                b += __shfl_xor_sync(0xFFFFFFFFu, b, m);
            if (lid == 0) {
                out[0]   = b * inv_scale;   // LAMBDA1 = 1.0
                g_ticket = 0;               // reset for next graph replay
            }
        }
    }
}

extern "C" void kernel_launch(void* const* d_in, const int* in_sizes, int n_in,
                              void* d_out, int out_size) {
    const float4* y4  = (const float4*)d_in[0];
    long long n_elems = (long long)in_sizes[0];   // N * D
    long long nvec    = n_elems / 4;
    float inv_scale   = (float)(1.0 / (double)n_elems);

    loss_kernel<<<NBLOCKS, NTHREADS>>>(y4, nvec, (float*)d_out, inv_scale);
}